// round 2
// baseline (speedup 1.0000x reference)
#include <cuda_runtime.h>

#define L 4096
#define C 64
#define NB 4

// Scratch (device globals -- allocation in kernel_launch is forbidden).
__device__ float g_M[NB][L * L];   // M, later overwritten with S  (256 MB)
__device__ float g_E[NB][L * L];   // exp(10*(s-rowmax)); later split-K partials
__device__ float g_rinv[NB][L];    // 1/rowsum per p

// ---- packed fp32x2 helpers ----
__device__ __forceinline__ unsigned long long pack2(float x, float y) {
    unsigned long long r;
    asm("mov.b64 %0, {%1, %2};" : "=l"(r) : "f"(x), "f"(y));
    return r;
}
__device__ __forceinline__ void fma2(unsigned long long &d, unsigned long long a,
                                     unsigned long long b) {
    asm("fma.rn.f32x2 %0, %1, %2, %3;" : "=l"(d) : "l"(a), "l"(b), "l"(d));
}

// ============================================================
// K1: M[p,l] = sum_c f[c,p]*b[c,l]   128x128 tile, 8x8/thread
// ============================================================
__global__ __launch_bounds__(256) void k_gemm_M(const float *__restrict__ fin,
                                                const float *__restrict__ bin) {
    __shared__ float As[32][128];  // [c][p]
    __shared__ float Bs[32][128];  // [c][l]
    const int bt = blockIdx.z;
    const int p0 = blockIdx.y << 7;
    const int l0 = blockIdx.x << 7;
    const float *fb = fin + bt * (C * L);
    const float *bb = bin + bt * (C * L);
    const int tid = threadIdx.x;
    const int tx = tid & 15, ty = tid >> 4;
    unsigned long long acc[8][4] = {};

    for (int kt = 0; kt < 2; kt++) {
        __syncthreads();
#pragma unroll
        for (int i = 0; i < 4; i++) {
            int idx = tid + (i << 8);          // float4 index, 1024 total
            int c = idx >> 5, x4 = idx & 31;
            *(float4 *)&As[c][x4 << 2] =
                *(const float4 *)&fb[(kt * 32 + c) * L + p0 + (x4 << 2)];
            *(float4 *)&Bs[c][x4 << 2] =
                *(const float4 *)&bb[(kt * 32 + c) * L + l0 + (x4 << 2)];
        }
        __syncthreads();
#pragma unroll 8
        for (int c = 0; c < 32; c++) {
            float4 a0 = *(const float4 *)&As[c][ty << 3];
            float4 a1 = *(const float4 *)&As[c][(ty << 3) + 4];
            ulonglong2 b0 = *(const ulonglong2 *)&Bs[c][tx << 3];
            ulonglong2 b1 = *(const ulonglong2 *)&Bs[c][(tx << 3) + 4];
            unsigned long long ap[8];
            ap[0] = pack2(a0.x, a0.x); ap[1] = pack2(a0.y, a0.y);
            ap[2] = pack2(a0.z, a0.z); ap[3] = pack2(a0.w, a0.w);
            ap[4] = pack2(a1.x, a1.x); ap[5] = pack2(a1.y, a1.y);
            ap[6] = pack2(a1.z, a1.z); ap[7] = pack2(a1.w, a1.w);
#pragma unroll
            for (int i = 0; i < 8; i++) {
                fma2(acc[i][0], ap[i], b0.x);
                fma2(acc[i][1], ap[i], b0.y);
                fma2(acc[i][2], ap[i], b1.x);
                fma2(acc[i][3], ap[i], b1.y);
            }
        }
    }
    float *out = g_M[bt];
#pragma unroll
    for (int i = 0; i < 8; i++) {
        const int row = p0 + (ty << 3) + i;
        ulonglong2 v0; v0.x = acc[i][0]; v0.y = acc[i][1];
        ulonglong2 v1; v1.x = acc[i][2]; v1.y = acc[i][3];
        *(ulonglong2 *)&out[row * L + l0 + (tx << 3)] = v0;
        *(ulonglong2 *)&out[row * L + l0 + (tx << 3) + 4] = v1;
    }
}

// ============================================================
// K2: scores stencil + softmax stats.  Block = 4 consecutive p
// (same py row), l-chunks of 512 staged in smem (18 rows x 516).
// ============================================================
__global__ __launch_bounds__(256) void k_score_softmax() {
    const int bt = blockIdx.y;
    const int g = blockIdx.x;          // 1024 groups
    const int py = g >> 4;
    const int px0 = (g & 15) << 2;
    const int pbase = py * 64 + px0;
    const float *__restrict__ M = g_M[bt];
    const int t = threadIdx.x;
    __shared__ float sm[18][516];
    __shared__ float4 red[8];

    float sreg[4][16];

    for (int chunk = 0; chunk < 8; chunk++) {
        const int l0 = chunk << 9;
        __syncthreads();
        // load 18 row-windows (zero-filled where p invalid / l OOB)
#pragma unroll
        for (int i = 0; i < 10; i++) {
            int idx = t + (i << 8);
            if (idx < 2322) {
                int r = idx / 129;
                int s4 = idx - r * 129;
                int dy = r / 6 - 1;
                int dxp = r - (r / 6) * 6 - 1;
                int prow_y = py + dy, prow_x = px0 + dxp;
                bool vrow = (unsigned)prow_y < 64u && (unsigned)prow_x < 64u;
                int grow = prow_y * 64 + prow_x;
                int base = l0 + dy * 64 - 1 + (s4 << 2);
#pragma unroll
                for (int k = 0; k < 4; k++) {
                    int gl = base + k;
                    sm[r][(s4 << 2) + k] =
                        (vrow && (unsigned)gl < 4096u) ? M[grow * L + gl] : 0.f;
                }
            }
        }
        __syncthreads();
#pragma unroll
        for (int half = 0; half < 2; half++) {
            const int lo = (half << 8) + t;      // l - l0
            const int l = l0 + lo;
            const int ly = l >> 6, lx = l & 63;
            float a0 = 0.f, a1 = 0.f, a2 = 0.f, a3 = 0.f;
#pragma unroll
            for (int dy = -1; dy <= 1; dy++) {
                if ((unsigned)(ly + dy) >= 64u) continue;
                const int rb = (dy + 1) * 6;
#pragma unroll
                for (int dx = -1; dx <= 1; dx++) {
                    if ((unsigned)(lx + dx) >= 64u) continue;
                    const int si = lo + dx + 1;
                    const int r0 = rb + dx + 1;
                    a0 += sm[r0][si];
                    a1 += sm[r0 + 1][si];
                    a2 += sm[r0 + 2][si];
                    a3 += sm[r0 + 3][si];
                }
            }
            sreg[0][(chunk << 1) + half] = a0;
            sreg[1][(chunk << 1) + half] = a1;
            sreg[2][(chunk << 1) + half] = a2;
            sreg[3][(chunk << 1) + half] = a3;
        }
    }

    // row maxes (4 rows at once, float4 lanes)
    float4 m;
    m.x = sreg[0][0]; m.y = sreg[1][0]; m.z = sreg[2][0]; m.w = sreg[3][0];
#pragma unroll
    for (int k = 1; k < 16; k++) {
        m.x = fmaxf(m.x, sreg[0][k]); m.y = fmaxf(m.y, sreg[1][k]);
        m.z = fmaxf(m.z, sreg[2][k]); m.w = fmaxf(m.w, sreg[3][k]);
    }
#pragma unroll
    for (int o = 16; o; o >>= 1) {
        m.x = fmaxf(m.x, __shfl_xor_sync(~0u, m.x, o));
        m.y = fmaxf(m.y, __shfl_xor_sync(~0u, m.y, o));
        m.z = fmaxf(m.z, __shfl_xor_sync(~0u, m.z, o));
        m.w = fmaxf(m.w, __shfl_xor_sync(~0u, m.w, o));
    }
    __syncthreads();
    if ((t & 31) == 0) red[t >> 5] = m;
    __syncthreads();
    float4 rm = red[0];
#pragma unroll
    for (int w = 1; w < 8; w++) {
        rm.x = fmaxf(rm.x, red[w].x); rm.y = fmaxf(rm.y, red[w].y);
        rm.z = fmaxf(rm.z, red[w].z); rm.w = fmaxf(rm.w, red[w].w);
    }

    float4 s4v = make_float4(0.f, 0.f, 0.f, 0.f);
#pragma unroll
    for (int k = 0; k < 16; k++) {
        float e0 = __expf(10.f * (sreg[0][k] - rm.x)); sreg[0][k] = e0; s4v.x += e0;
        float e1 = __expf(10.f * (sreg[1][k] - rm.y)); sreg[1][k] = e1; s4v.y += e1;
        float e2 = __expf(10.f * (sreg[2][k] - rm.z)); sreg[2][k] = e2; s4v.z += e2;
        float e3 = __expf(10.f * (sreg[3][k] - rm.w)); sreg[3][k] = e3; s4v.w += e3;
    }
#pragma unroll
    for (int o = 16; o; o >>= 1) {
        s4v.x += __shfl_xor_sync(~0u, s4v.x, o);
        s4v.y += __shfl_xor_sync(~0u, s4v.y, o);
        s4v.z += __shfl_xor_sync(~0u, s4v.z, o);
        s4v.w += __shfl_xor_sync(~0u, s4v.w, o);
    }
    __syncthreads();
    if ((t & 31) == 0) red[t >> 5] = s4v;
    __syncthreads();
    if (t == 0) {
        float4 tot = red[0];
#pragma unroll
        for (int w = 1; w < 8; w++) {
            tot.x += red[w].x; tot.y += red[w].y;
            tot.z += red[w].z; tot.w += red[w].w;
        }
        g_rinv[bt][pbase + 0] = 1.f / tot.x;
        g_rinv[bt][pbase + 1] = 1.f / tot.y;
        g_rinv[bt][pbase + 2] = 1.f / tot.z;
        g_rinv[bt][pbase + 3] = 1.f / tot.w;
    }

    float *E = g_E[bt];
#pragma unroll
    for (int k = 0; k < 16; k++) {
        const int l = ((k >> 1) << 9) + ((k & 1) << 8) + t;
        E[(pbase + 0) * L + l] = sreg[0][k];
        E[(pbase + 1) * L + l] = sreg[1][k];
        E[(pbase + 2) * L + l] = sreg[2][k];
        E[(pbase + 3) * L + l] = sreg[3][k];
    }
}

// ============================================================
// K3: S[p,l] = (1/9) sum_d E[p+d,l+d]*rinv[p+d]  (same tiling)
// rinv premultiplied at smem load.  Writes into g_M.
// ============================================================
__global__ __launch_bounds__(256) void k_attn_S() {
    const int bt = blockIdx.y;
    const int g = blockIdx.x;
    const int py = g >> 4;
    const int px0 = (g & 15) << 2;
    const int pbase = py * 64 + px0;
    const float *__restrict__ E = g_E[bt];
    const float *__restrict__ ri = g_rinv[bt];
    float *__restrict__ S = g_M[bt];
    const int t = threadIdx.x;
    __shared__ float sm[18][516];

    for (int chunk = 0; chunk < 8; chunk++) {
        const int l0 = chunk << 9;
        __syncthreads();
#pragma unroll
        for (int i = 0; i < 10; i++) {
            int idx = t + (i << 8);
            if (idx < 2322) {
                int r = idx / 129;
                int s4 = idx - r * 129;
                int dy = r / 6 - 1;
                int dxp = r - (r / 6) * 6 - 1;
                int prow_y = py + dy, prow_x = px0 + dxp;
                bool vrow = (unsigned)prow_y < 64u && (unsigned)prow_x < 64u;
                int grow = prow_y * 64 + prow_x;
                float rv = vrow ? ri[grow] : 0.f;
                int base = l0 + dy * 64 - 1 + (s4 << 2);
#pragma unroll
                for (int k = 0; k < 4; k++) {
                    int gl = base + k;
                    sm[r][(s4 << 2) + k] =
                        (vrow && (unsigned)gl < 4096u) ? E[grow * L + gl] * rv : 0.f;
                }
            }
        }
        __syncthreads();
#pragma unroll
        for (int half = 0; half < 2; half++) {
            const int lo = (half << 8) + t;
            const int l = l0 + lo;
            const int ly = l >> 6, lx = l & 63;
            float a0 = 0.f, a1 = 0.f, a2 = 0.f, a3 = 0.f;
#pragma unroll
            for (int dy = -1; dy <= 1; dy++) {
                if ((unsigned)(ly + dy) >= 64u) continue;
                const int rb = (dy + 1) * 6;
#pragma unroll
                for (int dx = -1; dx <= 1; dx++) {
                    if ((unsigned)(lx + dx) >= 64u) continue;
                    const int si = lo + dx + 1;
                    const int r0 = rb + dx + 1;
                    a0 += sm[r0][si];
                    a1 += sm[r0 + 1][si];
                    a2 += sm[r0 + 2][si];
                    a3 += sm[r0 + 3][si];
                }
            }
            S[(pbase + 0) * L + l] = a0 * (1.f / 9.f);
            S[(pbase + 1) * L + l] = a1 * (1.f / 9.f);
            S[(pbase + 2) * L + l] = a2 * (1.f / 9.f);
            S[(pbase + 3) * L + l] = a3 * (1.f / 9.f);
        }
    }
}

// ============================================================
// K4: split-K GEMM  y[c,p] = sum_l S[p,l]*b[c,l]
// grid (32 p-tiles, 8 k-splits, NB); 128 threads; 8x8/thread.
// Partials into g_E (free after K3).
// ============================================================
__global__ __launch_bounds__(128) void k_gemm_y(const float *__restrict__ bin) {
    __shared__ float Ss[32][132];  // [l][p]
    __shared__ float Bt[32][68];   // [l][c]
    const int bt = blockIdx.z;
    const int ks = blockIdx.y;
    const int p0 = blockIdx.x << 7;
    const float *S = g_M[bt];
    const float *bb = bin + bt * (C * L);
    const int tid = threadIdx.x;
    const int tx = tid & 15, ty = tid >> 4;  // tx->p(8), ty->c(8)
    unsigned long long acc[8][4] = {};

    for (int lt = ks << 9; lt < (ks + 1) << 9; lt += 32) {
        __syncthreads();
#pragma unroll
        for (int i = 0; i < 8; i++) {
            int idx = tid + (i << 7);          // 1024 float4s of S tile
            int r = idx >> 3, q4 = idx & 7;
            float4 v = *(const float4 *)&S[(p0 + r) * L + lt + (q4 << 2)];
            Ss[(q4 << 2) + 0][r] = v.x;
            Ss[(q4 << 2) + 1][r] = v.y;
            Ss[(q4 << 2) + 2][r] = v.z;
            Ss[(q4 << 2) + 3][r] = v.w;
        }
#pragma unroll
        for (int i = 0; i < 4; i++) {
            int idx = tid + (i << 7);          // 512 float4s of b tile
            int r = idx >> 3, q4 = idx & 7;
            float4 v = *(const float4 *)&bb[r * L + lt + (q4 << 2)];
            Bt[(q4 << 2) + 0][r] = v.x;
            Bt[(q4 << 2) + 1][r] = v.y;
            Bt[(q4 << 2) + 2][r] = v.z;
            Bt[(q4 << 2) + 3][r] = v.w;
        }
        __syncthreads();
#pragma unroll 8
        for (int l = 0; l < 32; l++) {
            ulonglong2 s0 = *(const ulonglong2 *)&Ss[l][tx << 3];
            ulonglong2 s1 = *(const ulonglong2 *)&Ss[l][(tx << 3) + 4];
            float4 b0 = *(const float4 *)&Bt[l][ty << 3];
            float4 b1 = *(const float4 *)&Bt[l][(ty << 3) + 4];
            unsigned long long ap[8];
            ap[0] = pack2(b0.x, b0.x); ap[1] = pack2(b0.y, b0.y);
            ap[2] = pack2(b0.z, b0.z); ap[3] = pack2(b0.w, b0.w);
            ap[4] = pack2(b1.x, b1.x); ap[5] = pack2(b1.y, b1.y);
            ap[6] = pack2(b1.z, b1.z); ap[7] = pack2(b1.w, b1.w);
#pragma unroll
            for (int ci = 0; ci < 8; ci++) {
                fma2(acc[ci][0], ap[ci], s0.x);
                fma2(acc[ci][1], ap[ci], s0.y);
                fma2(acc[ci][2], ap[ci], s1.x);
                fma2(acc[ci][3], ap[ci], s1.y);
            }
        }
    }
    float *part = (float *)g_E;
#pragma unroll
    for (int ci = 0; ci < 8; ci++) {
        const int c = (ty << 3) + ci;
        float *dst = part + (((bt << 3) + ks) * 64 + c) * L + p0 + (tx << 3);
        ulonglong2 v0; v0.x = acc[ci][0]; v0.y = acc[ci][1];
        ulonglong2 v1; v1.x = acc[ci][2]; v1.y = acc[ci][3];
        *(ulonglong2 *)dst = v0;
        *(ulonglong2 *)(dst + 4) = v1;
    }
}

// reduce the 8 split-K partials into y
__global__ __launch_bounds__(256) void k_reduce_y(float *__restrict__ yout) {
    const int i = blockIdx.x * 256 + threadIdx.x;   // float4 index, 262144 total
    const int p4 = i & 1023;
    const int c = (i >> 10) & 63;
    const int bt = i >> 16;
    const float4 *part = (const float4 *)g_E;
    float4 s = make_float4(0.f, 0.f, 0.f, 0.f);
#pragma unroll
    for (int ks = 0; ks < 8; ks++) {
        float4 v = part[(((bt << 3) + ks) * 64 + c) * 1024 + p4];
        s.x += v.x; s.y += v.y; s.z += v.z; s.w += v.w;
    }
    ((float4 *)yout)[(bt * 64 + c) * 1024 + p4] = s;
}

// ============================================================
// K5: w output: w[b,l,c,i,j] = b[c, l + (i-1,j-1)]  (0 when OOB)
// ============================================================
__global__ __launch_bounds__(256) void k_wout(const float *__restrict__ bin,
                                              float *__restrict__ wout) {
    const int idx = blockIdx.x * 256 + threadIdx.x;
    const int j3 = idx % 9;
    const int c = (idx / 9) & 63;
    const int l = (idx / 576) & 4095;
    const int bt = idx / (576 * 4096);
    const int dy = j3 / 3 - 1, dx = j3 % 3 - 1;
    const int ly = l >> 6, lx = l & 63;
    float v = 0.f;
    if ((unsigned)(ly + dy) < 64u && (unsigned)(lx + dx) < 64u)
        v = bin[bt * (C * L) + c * L + l + dy * 64 + dx];
    wout[idx] = v;
}

extern "C" void kernel_launch(void *const *d_in, const int *in_sizes, int n_in,
                              void *d_out, int out_size) {
    const float *f = (const float *)d_in[0];
    const float *b = (const float *)d_in[1];
    float *out = (float *)d_out;

    k_gemm_M<<<dim3(32, 32, NB), 256>>>(f, b);
    k_score_softmax<<<dim3(1024, NB), 256>>>();
    k_attn_S<<<dim3(1024, NB), 256>>>();
    k_gemm_y<<<dim3(32, 8, NB), 128>>>(b);
    k_reduce_y<<<1024, 256>>>(out);
    k_wout<<<(NB * L * C * 9) / 256, 256>>>(b, out + NB * C * L);
}

// round 3
// speedup vs baseline: 1.5618x; 1.5618x over previous
#include <cuda_runtime.h>

#define L 4096
#define C 64
#define NB 4

// Scratch (device globals -- allocation in kernel_launch is forbidden).
__device__ float g_M[NB][L * L];   // M, later overwritten with S  (256 MB)
__device__ float g_E[NB][L * L];   // exp(10*(s-rowmax)); later split-K partials
__device__ float g_rinv[NB][L];    // 1/rowsum per p

// ---- packed fp32x2 helpers ----
__device__ __forceinline__ unsigned long long pack2(float x, float y) {
    unsigned long long r;
    asm("mov.b64 %0, {%1, %2};" : "=l"(r) : "f"(x), "f"(y));
    return r;
}
__device__ __forceinline__ void fma2(unsigned long long &d, unsigned long long a,
                                     unsigned long long b) {
    asm("fma.rn.f32x2 %0, %1, %2, %3;" : "=l"(d) : "l"(a), "l"(b), "l"(d));
}

// ============================================================
// K1: M[p,l] = sum_c f[c,p]*b[c,l]   128x128 tile, 8x8/thread
// ============================================================
__global__ __launch_bounds__(256) void k_gemm_M(const float *__restrict__ fin,
                                                const float *__restrict__ bin) {
    __shared__ float As[32][128];  // [c][p]
    __shared__ float Bs[32][128];  // [c][l]
    const int bt = blockIdx.z;
    const int p0 = blockIdx.y << 7;
    const int l0 = blockIdx.x << 7;
    const float *fb = fin + bt * (C * L);
    const float *bb = bin + bt * (C * L);
    const int tid = threadIdx.x;
    const int tx = tid & 15, ty = tid >> 4;
    unsigned long long acc[8][4] = {};

    for (int kt = 0; kt < 2; kt++) {
        __syncthreads();
#pragma unroll
        for (int i = 0; i < 4; i++) {
            int idx = tid + (i << 8);          // float4 index, 1024 total
            int c = idx >> 5, x4 = idx & 31;
            *(float4 *)&As[c][x4 << 2] =
                *(const float4 *)&fb[(kt * 32 + c) * L + p0 + (x4 << 2)];
            *(float4 *)&Bs[c][x4 << 2] =
                *(const float4 *)&bb[(kt * 32 + c) * L + l0 + (x4 << 2)];
        }
        __syncthreads();
#pragma unroll 8
        for (int c = 0; c < 32; c++) {
            float4 a0 = *(const float4 *)&As[c][ty << 3];
            float4 a1 = *(const float4 *)&As[c][(ty << 3) + 4];
            ulonglong2 b0 = *(const ulonglong2 *)&Bs[c][tx << 3];
            ulonglong2 b1 = *(const ulonglong2 *)&Bs[c][(tx << 3) + 4];
            unsigned long long ap[8];
            ap[0] = pack2(a0.x, a0.x); ap[1] = pack2(a0.y, a0.y);
            ap[2] = pack2(a0.z, a0.z); ap[3] = pack2(a0.w, a0.w);
            ap[4] = pack2(a1.x, a1.x); ap[5] = pack2(a1.y, a1.y);
            ap[6] = pack2(a1.z, a1.z); ap[7] = pack2(a1.w, a1.w);
#pragma unroll
            for (int i = 0; i < 8; i++) {
                fma2(acc[i][0], ap[i], b0.x);
                fma2(acc[i][1], ap[i], b0.y);
                fma2(acc[i][2], ap[i], b1.x);
                fma2(acc[i][3], ap[i], b1.y);
            }
        }
    }
    float *out = g_M[bt];
#pragma unroll
    for (int i = 0; i < 8; i++) {
        const int row = p0 + (ty << 3) + i;
        ulonglong2 v0; v0.x = acc[i][0]; v0.y = acc[i][1];
        ulonglong2 v1; v1.x = acc[i][2]; v1.y = acc[i][3];
        *(ulonglong2 *)&out[row * L + l0 + (tx << 3)] = v0;
        *(ulonglong2 *)&out[row * L + l0 + (tx << 3) + 4] = v1;
    }
}

// ============================================================
// K2 (round-1 form): scores[p,l] = sum_d valid M[p+d,l+d]
//     then row softmax: E = exp(10*(s-rowmax)), rinv = 1/rowsum
// ============================================================
__global__ __launch_bounds__(256) void k_score_softmax() {
    const int bt = blockIdx.y;
    const int p = blockIdx.x;
    const int py = p >> 6, px = p & 63;
    const float *__restrict__ M = g_M[bt];
    const int t = threadIdx.x;
    __shared__ float redA[8], redB[8];

    float s[16];
#pragma unroll
    for (int k = 0; k < 16; k++) {
        const int l = t + (k << 8);
        const int ly = l >> 6, lx = l & 63;
        float acc = 0.f;
#pragma unroll
        for (int dy = -1; dy <= 1; dy++) {
#pragma unroll
            for (int dx = -1; dx <= 1; dx++) {
                if ((unsigned)(py + dy) < 64u && (unsigned)(px + dx) < 64u &&
                    (unsigned)(ly + dy) < 64u && (unsigned)(lx + dx) < 64u) {
                    const int off = dy * 64 + dx;
                    acc += M[(p + off) * L + l + off];
                }
            }
        }
        s[k] = acc;
    }
    float m = s[0];
#pragma unroll
    for (int k = 1; k < 16; k++) m = fmaxf(m, s[k]);
#pragma unroll
    for (int o = 16; o; o >>= 1) m = fmaxf(m, __shfl_xor_sync(0xffffffffu, m, o));
    if ((t & 31) == 0) redA[t >> 5] = m;
    __syncthreads();
    float rowmax = redA[0];
#pragma unroll
    for (int i = 1; i < 8; i++) rowmax = fmaxf(rowmax, redA[i]);

    float sum = 0.f;
#pragma unroll
    for (int k = 0; k < 16; k++) {
        float e = __expf(10.f * (s[k] - rowmax));
        s[k] = e;
        sum += e;
    }
#pragma unroll
    for (int o = 16; o; o >>= 1) sum += __shfl_xor_sync(0xffffffffu, sum, o);
    if ((t & 31) == 0) redB[t >> 5] = sum;
    __syncthreads();

    float *E = g_E[bt] + p * L;
#pragma unroll
    for (int k = 0; k < 16; k++) E[t + (k << 8)] = s[k];

    if (t == 0) {
        float tot = 0.f;
#pragma unroll
        for (int i = 0; i < 8; i++) tot += redB[i];
        g_rinv[bt][p] = 1.f / tot;
    }
}

// ============================================================
// K3 (round-1 form): S[p,l] = (1/9) sum_d E[p+d,l+d]*rinv[p+d]
// ============================================================
__global__ __launch_bounds__(256) void k_attn_S() {
    const int bt = blockIdx.y;
    const int p = blockIdx.x;
    const int py = p >> 6, px = p & 63;
    const float *__restrict__ E = g_E[bt];
    const float *__restrict__ ri = g_rinv[bt];
    const int t = threadIdx.x;

    float rv[9];
    bool pv[9];
    {
        int i = 0;
#pragma unroll
        for (int dy = -1; dy <= 1; dy++)
#pragma unroll
            for (int dx = -1; dx <= 1; dx++) {
                bool ok = (unsigned)(py + dy) < 64u && (unsigned)(px + dx) < 64u;
                pv[i] = ok;
                rv[i] = ok ? ri[p + dy * 64 + dx] : 0.f;
                i++;
            }
    }

    float *out = g_M[bt] + p * L;
#pragma unroll
    for (int k = 0; k < 16; k++) {
        const int l = t + (k << 8);
        const int ly = l >> 6, lx = l & 63;
        float acc = 0.f;
        int i = 0;
#pragma unroll
        for (int dy = -1; dy <= 1; dy++)
#pragma unroll
            for (int dx = -1; dx <= 1; dx++) {
                if (pv[i] && (unsigned)(ly + dy) < 64u && (unsigned)(lx + dx) < 64u) {
                    const int off = dy * 64 + dx;
                    acc += E[(p + off) * L + l + off] * rv[i];
                }
                i++;
            }
        out[l] = acc * (1.f / 9.f);
    }
}

// ============================================================
// K4: split-K GEMM  y[c,p] = sum_l S[p,l]*b[c,l]
// grid (32 p-tiles, 8 k-splits, NB); 128 threads; 8x8/thread.
// ============================================================
__global__ __launch_bounds__(128) void k_gemm_y(const float *__restrict__ bin) {
    __shared__ float Ss[32][132];  // [l][p]
    __shared__ float Bt[32][68];   // [l][c]
    const int bt = blockIdx.z;
    const int ks = blockIdx.y;
    const int p0 = blockIdx.x << 7;
    const float *S = g_M[bt];
    const float *bb = bin + bt * (C * L);
    const int tid = threadIdx.x;
    const int tx = tid & 15, ty = tid >> 4;  // tx->p(8), ty->c(8)
    unsigned long long acc[8][4] = {};

    for (int lt = ks << 9; lt < (ks + 1) << 9; lt += 32) {
        __syncthreads();
#pragma unroll
        for (int i = 0; i < 8; i++) {
            int idx = tid + (i << 7);          // 1024 float4s of S tile
            int r = idx >> 3, q4 = idx & 7;
            float4 v = *(const float4 *)&S[(p0 + r) * L + lt + (q4 << 2)];
            Ss[(q4 << 2) + 0][r] = v.x;
            Ss[(q4 << 2) + 1][r] = v.y;
            Ss[(q4 << 2) + 2][r] = v.z;
            Ss[(q4 << 2) + 3][r] = v.w;
        }
#pragma unroll
        for (int i = 0; i < 4; i++) {
            int idx = tid + (i << 7);          // 512 float4s of b tile
            int r = idx >> 3, q4 = idx & 7;
            float4 v = *(const float4 *)&bb[r * L + lt + (q4 << 2)];
            Bt[(q4 << 2) + 0][r] = v.x;
            Bt[(q4 << 2) + 1][r] = v.y;
            Bt[(q4 << 2) + 2][r] = v.z;
            Bt[(q4 << 2) + 3][r] = v.w;
        }
        __syncthreads();
#pragma unroll 8
        for (int l = 0; l < 32; l++) {
            ulonglong2 s0 = *(const ulonglong2 *)&Ss[l][tx << 3];
            ulonglong2 s1 = *(const ulonglong2 *)&Ss[l][(tx << 3) + 4];
            float4 b0 = *(const float4 *)&Bt[l][ty << 3];
            float4 b1 = *(const float4 *)&Bt[l][(ty << 3) + 4];
            unsigned long long ap[8];
            ap[0] = pack2(b0.x, b0.x); ap[1] = pack2(b0.y, b0.y);
            ap[2] = pack2(b0.z, b0.z); ap[3] = pack2(b0.w, b0.w);
            ap[4] = pack2(b1.x, b1.x); ap[5] = pack2(b1.y, b1.y);
            ap[6] = pack2(b1.z, b1.z); ap[7] = pack2(b1.w, b1.w);
#pragma unroll
            for (int ci = 0; ci < 8; ci++) {
                fma2(acc[ci][0], ap[ci], s0.x);
                fma2(acc[ci][1], ap[ci], s0.y);
                fma2(acc[ci][2], ap[ci], s1.x);
                fma2(acc[ci][3], ap[ci], s1.y);
            }
        }
    }
    float *part = (float *)g_E;
#pragma unroll
    for (int ci = 0; ci < 8; ci++) {
        const int c = (ty << 3) + ci;
        float *dst = part + (((bt << 3) + ks) * 64 + c) * L + p0 + (tx << 3);
        ulonglong2 v0; v0.x = acc[ci][0]; v0.y = acc[ci][1];
        ulonglong2 v1; v1.x = acc[ci][2]; v1.y = acc[ci][3];
        *(ulonglong2 *)dst = v0;
        *(ulonglong2 *)(dst + 4) = v1;
    }
}

// reduce the 8 split-K partials into y
__global__ __launch_bounds__(256) void k_reduce_y(float *__restrict__ yout) {
    const int i = blockIdx.x * 256 + threadIdx.x;   // float4 index, 262144 total
    const int p4 = i & 1023;
    const int c = (i >> 10) & 63;
    const int bt = i >> 16;
    const float4 *part = (const float4 *)g_E;
    float4 s = make_float4(0.f, 0.f, 0.f, 0.f);
#pragma unroll
    for (int ks = 0; ks < 8; ks++) {
        float4 v = part[(((bt << 3) + ks) * 64 + c) * 1024 + p4];
        s.x += v.x; s.y += v.y; s.z += v.z; s.w += v.w;
    }
    ((float4 *)yout)[(bt * 64 + c) * 1024 + p4] = s;
}

// ============================================================
// K5: w output: w[b,l,c,i,j] = b[c, l + (i-1,j-1)]  (0 when OOB)
// ============================================================
__global__ __launch_bounds__(256) void k_wout(const float *__restrict__ bin,
                                              float *__restrict__ wout) {
    const int idx = blockIdx.x * 256 + threadIdx.x;
    const int j3 = idx % 9;
    const int c = (idx / 9) & 63;
    const int l = (idx / 576) & 4095;
    const int bt = idx / (576 * 4096);
    const int dy = j3 / 3 - 1, dx = j3 % 3 - 1;
    const int ly = l >> 6, lx = l & 63;
    float v = 0.f;
    if ((unsigned)(ly + dy) < 64u && (unsigned)(lx + dx) < 64u)
        v = bin[bt * (C * L) + c * L + l + dy * 64 + dx];
    wout[idx] = v;
}

extern "C" void kernel_launch(void *const *d_in, const int *in_sizes, int n_in,
                              void *d_out, int out_size) {
    const float *f = (const float *)d_in[0];
    const float *b = (const float *)d_in[1];
    float *out = (float *)d_out;

    k_gemm_M<<<dim3(32, 32, NB), 256>>>(f, b);
    k_score_softmax<<<dim3(L, NB), 256>>>();
    k_attn_S<<<dim3(L, NB), 256>>>();
    k_gemm_y<<<dim3(32, 8, NB), 128>>>(b);
    k_reduce_y<<<1024, 256>>>(out);
    k_wout<<<(NB * L * C * 9) / 256, 256>>>(b, out + NB * C * L);
}